// round 1
// baseline (speedup 1.0000x reference)
#include <cuda_runtime.h>
#include <math.h>

#define BATCH 4
#define SEQ   4096
#define DIN   1024
#define DH    64
#define PAD   68   // floats per smem row: 16B-aligned, bank-conflict-free

// Scratch for Q/K/V projections (4 MB each) — __device__ globals, no allocation.
__device__ float g_Q[BATCH * SEQ * DH];
__device__ float g_K[BATCH * SEQ * DH];
__device__ float g_V[BATCH * SEQ * DH];

// ---------------------------------------------------------------------------
// QKV projection GEMM: Out[M,64] = X[M,1024] @ W[1024,64],  M = B*S = 16384
// grid: (M/64, 3)  block: 256 threads (16x16), each thread 4x4 micro-tile
// ---------------------------------------------------------------------------
__global__ __launch_bounds__(256) void qkv_gemm(const float* __restrict__ X,
                                                const float* __restrict__ Wq,
                                                const float* __restrict__ Wk,
                                                const float* __restrict__ Wv) {
    __shared__ float Xs[64][17];
    __shared__ float Ws[16][PAD];

    const float* W   = (blockIdx.y == 0) ? Wq : (blockIdx.y == 1) ? Wk : Wv;
    float*       Out = (blockIdx.y == 0) ? g_Q : (blockIdx.y == 1) ? g_K : g_V;

    const int tid  = threadIdx.x;
    const int row0 = blockIdx.x * 64;
    const int tx   = tid & 15;   // output col group
    const int ty   = tid >> 4;   // output row group

    float acc[4][4];
#pragma unroll
    for (int i = 0; i < 4; i++)
#pragma unroll
        for (int j = 0; j < 4; j++) acc[i][j] = 0.f;

    for (int k0 = 0; k0 < DIN; k0 += 16) {
        // Load X tile 64x16 (one float4 per thread)
        {
            int r = tid >> 2, c4 = tid & 3;
            float4 v = *(const float4*)(X + (size_t)(row0 + r) * DIN + k0 + c4 * 4);
            Xs[r][c4 * 4 + 0] = v.x; Xs[r][c4 * 4 + 1] = v.y;
            Xs[r][c4 * 4 + 2] = v.z; Xs[r][c4 * 4 + 3] = v.w;
        }
        // Load W tile 16x64 (one float4 per thread)
        {
            int r = tid >> 4, c4 = tid & 15;
            float4 v = *(const float4*)(W + (size_t)(k0 + r) * DH + c4 * 4);
            *(float4*)&Ws[r][c4 * 4] = v;
        }
        __syncthreads();

#pragma unroll
        for (int kk = 0; kk < 16; kk++) {
            float a[4];
#pragma unroll
            for (int i = 0; i < 4; i++) a[i] = Xs[ty * 4 + i][kk];
            float4 b4 = *(float4*)&Ws[kk][tx * 4];
            float b[4] = {b4.x, b4.y, b4.z, b4.w};
#pragma unroll
            for (int i = 0; i < 4; i++)
#pragma unroll
                for (int j = 0; j < 4; j++) acc[i][j] = fmaf(a[i], b[j], acc[i][j]);
        }
        __syncthreads();
    }

#pragma unroll
    for (int i = 0; i < 4; i++) {
        float4 v = make_float4(acc[i][0], acc[i][1], acc[i][2], acc[i][3]);
        *(float4*)(Out + (size_t)(row0 + ty * 4 + i) * DH + tx * 4) = v;
    }
}

// ---------------------------------------------------------------------------
// Causal flash attention, fp32, online softmax.
// BLOCK_M = BLOCK_N = 64, 256 threads = 4 threads per query row.
// Each block processes q-tile pair (x, 63-x) -> exactly 65 kv-tile-units/block.
// grid: (32, BATCH)
// smem: Qs + Ks + Vs, each 64 x PAD floats. P tile aliases Ks.
// ---------------------------------------------------------------------------
__global__ __launch_bounds__(256) void flash_attn(float* __restrict__ O) {
    extern __shared__ float sm[];
    float (*Qs)[PAD] = (float(*)[PAD])sm;
    float (*Ks)[PAD] = (float(*)[PAD])(sm + 64 * PAD);
    float (*Vs)[PAD] = (float(*)[PAD])(sm + 2 * 64 * PAD);
    float (*Ps)[PAD] = Ks;  // P reuses K's smem after scores are computed

    const int b   = blockIdx.y;
    const int tid = threadIdx.x;
    const int r   = tid >> 2;  // query row within tile (0..63)
    const int c   = tid & 3;   // lane within 4-thread row group
    const float scale = 0.125f;  // 64^-0.5

    for (int pass = 0; pass < 2; pass++) {
        const int qt = pass ? (63 - (int)blockIdx.x) : (int)blockIdx.x;
        const int i0 = qt * 64;
        const float* Qg = g_Q + ((size_t)b * SEQ + i0) * DH;

        // Load Q tile (pre-scaled)
        for (int idx = tid; idx < 64 * 16; idx += 256) {
            int rr = idx >> 4, c4 = idx & 15;
            float4 v = *(const float4*)(Qg + rr * DH + c4 * 4);
            v.x *= scale; v.y *= scale; v.z *= scale; v.w *= scale;
            *(float4*)&Qs[rr][c4 * 4] = v;
        }

        float m = -INFINITY, l = 0.f;
        float4 o[4];
#pragma unroll
        for (int i = 0; i < 4; i++) o[i] = make_float4(0.f, 0.f, 0.f, 0.f);

        const int ntiles = qt + 1;
        for (int t = 0; t < ntiles; t++) {
            const int j0 = t * 64;
            const float* Kg = g_K + ((size_t)b * SEQ + j0) * DH;
            const float* Vg = g_V + ((size_t)b * SEQ + j0) * DH;

            __syncthreads();  // prior-tile readers done; Q tile visible
            for (int idx = tid; idx < 64 * 16; idx += 256) {
                int rr = idx >> 4, c4 = idx & 15;
                *(float4*)&Ks[rr][c4 * 4] = *(const float4*)(Kg + rr * DH + c4 * 4);
                *(float4*)&Vs[rr][c4 * 4] = *(const float4*)(Vg + rr * DH + c4 * 4);
            }
            __syncthreads();

            // Scores: this thread owns keys k = c + 4*kk, kk = 0..15
            float s[16];
#pragma unroll
            for (int kk = 0; kk < 16; kk++) s[kk] = 0.f;
#pragma unroll 4
            for (int d4 = 0; d4 < 16; d4++) {
                float4 q4 = *(float4*)&Qs[r][d4 * 4];
#pragma unroll
                for (int kk = 0; kk < 16; kk++) {
                    float4 k4 = *(float4*)&Ks[c + kk * 4][d4 * 4];
                    s[kk] = fmaf(q4.x, k4.x, s[kk]);
                    s[kk] = fmaf(q4.y, k4.y, s[kk]);
                    s[kk] = fmaf(q4.z, k4.z, s[kk]);
                    s[kk] = fmaf(q4.w, k4.w, s[kk]);
                }
            }

            // Causal mask on the diagonal tile
            if (t == qt) {
#pragma unroll
                for (int kk = 0; kk < 16; kk++)
                    if (c + kk * 4 > r) s[kk] = -INFINITY;
            }

            // Online softmax (row reduction across the 4-thread group)
            float mt = s[0];
#pragma unroll
            for (int kk = 1; kk < 16; kk++) mt = fmaxf(mt, s[kk]);
            mt = fmaxf(mt, __shfl_xor_sync(0xffffffffu, mt, 1));
            mt = fmaxf(mt, __shfl_xor_sync(0xffffffffu, mt, 2));
            const float mnew  = fmaxf(m, mt);
            const float alpha = __expf(m - mnew);  // 0 when m == -inf

            float p[16];
            float lt = 0.f;
#pragma unroll
            for (int kk = 0; kk < 16; kk++) {
                p[kk] = __expf(s[kk] - mnew);  // masked -> exp(-inf) = 0
                lt += p[kk];
            }
            lt += __shfl_xor_sync(0xffffffffu, lt, 1);
            lt += __shfl_xor_sync(0xffffffffu, lt, 2);
            l = l * alpha + lt;
            m = mnew;
#pragma unroll
            for (int i = 0; i < 4; i++) {
                o[i].x *= alpha; o[i].y *= alpha; o[i].z *= alpha; o[i].w *= alpha;
            }

            __syncthreads();  // everyone done reading Ks before P overwrites it
#pragma unroll
            for (int kk = 0; kk < 16; kk++) Ps[r][c + kk * 4] = p[kk];
            __syncthreads();

            // O += P @ V : this thread owns output dims d = c*16 .. c*16+15
#pragma unroll 4
            for (int k = 0; k < 64; k++) {
                float pv = Ps[r][k];
#pragma unroll
                for (int i = 0; i < 4; i++) {
                    float4 v4 = *(float4*)&Vs[k][c * 16 + i * 4];
                    o[i].x = fmaf(pv, v4.x, o[i].x);
                    o[i].y = fmaf(pv, v4.y, o[i].y);
                    o[i].z = fmaf(pv, v4.z, o[i].z);
                    o[i].w = fmaf(pv, v4.w, o[i].w);
                }
            }
        }

        // Finalize and write
        const float inv = 1.f / l;
        float* Og = O + ((size_t)b * SEQ + i0 + r) * DH + c * 16;
#pragma unroll
        for (int i = 0; i < 4; i++) {
            float4 v = o[i];
            v.x *= inv; v.y *= inv; v.z *= inv; v.w *= inv;
            *(float4*)(Og + i * 4) = v;
        }
        __syncthreads();  // before next pass reloads Qs
    }
}

// ---------------------------------------------------------------------------
extern "C" void kernel_launch(void* const* d_in, const int* in_sizes, int n_in,
                              void* d_out, int out_size) {
    const float* X  = (const float*)d_in[0];
    const float* Wq = (const float*)d_in[1];
    const float* Wk = (const float*)d_in[2];
    const float* Wv = (const float*)d_in[3];
    float* O = (float*)d_out;

    const int smem_attn = 3 * 64 * PAD * sizeof(float);  // 52224 B > 48KB default
    cudaFuncSetAttribute(flash_attn, cudaFuncAttributeMaxDynamicSharedMemorySize,
                         smem_attn);

    dim3 gproj((BATCH * SEQ) / 64, 3);
    qkv_gemm<<<gproj, 256>>>(X, Wq, Wk, Wv);

    dim3 gattn(32, BATCH);
    flash_attn<<<gattn, 256, smem_attn>>>(O);
}

// round 2
// speedup vs baseline: 1.5442x; 1.5442x over previous
#include <cuda_runtime.h>
#include <math.h>

#define BATCH 4
#define SEQ   4096
#define DIN   1024
#define DH    64
#define PAD   68   // floats per smem row: 16B-aligned, conflict-benign

// Scratch for Q/K/V projections — __device__ globals, no allocation.
__device__ float g_Q[BATCH * SEQ * DH];
__device__ float g_K[BATCH * SEQ * DH];
__device__ float g_V[BATCH * SEQ * DH];

// ---------------------------------------------------------------------------
// QKV projection GEMM: Out[M,64] = X[M,1024] @ W[1024,64],  M = B*S = 16384
// grid: (M/64, 3)  block: 256 threads (16x16), each thread 4x4 micro-tile
// ---------------------------------------------------------------------------
__global__ __launch_bounds__(256) void qkv_gemm(const float* __restrict__ X,
                                                const float* __restrict__ Wq,
                                                const float* __restrict__ Wk,
                                                const float* __restrict__ Wv) {
    __shared__ float Xs[64][17];
    __shared__ float Ws[16][PAD];

    const float* W   = (blockIdx.y == 0) ? Wq : (blockIdx.y == 1) ? Wk : Wv;
    float*       Out = (blockIdx.y == 0) ? g_Q : (blockIdx.y == 1) ? g_K : g_V;

    const int tid  = threadIdx.x;
    const int row0 = blockIdx.x * 64;
    const int tx   = tid & 15;   // output col group
    const int ty   = tid >> 4;   // output row group

    float acc[4][4];
#pragma unroll
    for (int i = 0; i < 4; i++)
#pragma unroll
        for (int j = 0; j < 4; j++) acc[i][j] = 0.f;

    for (int k0 = 0; k0 < DIN; k0 += 16) {
        {
            int r = tid >> 2, c4 = tid & 3;
            float4 v = *(const float4*)(X + (size_t)(row0 + r) * DIN + k0 + c4 * 4);
            Xs[r][c4 * 4 + 0] = v.x; Xs[r][c4 * 4 + 1] = v.y;
            Xs[r][c4 * 4 + 2] = v.z; Xs[r][c4 * 4 + 3] = v.w;
        }
        {
            int r = tid >> 4, c4 = tid & 15;
            float4 v = *(const float4*)(W + (size_t)(k0 + r) * DH + c4 * 4);
            *(float4*)&Ws[r][c4 * 4] = v;
        }
        __syncthreads();

#pragma unroll
        for (int kk = 0; kk < 16; kk++) {
            float a[4];
#pragma unroll
            for (int i = 0; i < 4; i++) a[i] = Xs[ty * 4 + i][kk];
            float4 b4 = *(float4*)&Ws[kk][tx * 4];
            float b[4] = {b4.x, b4.y, b4.z, b4.w};
#pragma unroll
            for (int i = 0; i < 4; i++)
#pragma unroll
                for (int j = 0; j < 4; j++) acc[i][j] = fmaf(a[i], b[j], acc[i][j]);
        }
        __syncthreads();
    }

#pragma unroll
    for (int i = 0; i < 4; i++) {
        float4 v = make_float4(acc[i][0], acc[i][1], acc[i][2], acc[i][3]);
        *(float4*)(Out + (size_t)(row0 + ty * 4 + i) * DH + tx * 4) = v;
    }
}

// ---------------------------------------------------------------------------
// Causal flash attention, fp32, online softmax, 2-D register blocking.
// BLOCK_M = BLOCK_N = 64, 256 threads in a 16(tx) x 16(ty) grid.
// Each thread owns a 4x4 score block (rows ty*4.., keys/dims tx*4..).
// grid.x = 256 blocks. bid->qt mapping balances the causal workload so the
// two blocks co-resident on each SM (bid, bid+148) sum to 65 tile-units.
// smem: Qs, Ks, Vs, Ps — 4 x 64 x PAD floats = 69632 B dynamic.
// ---------------------------------------------------------------------------
__global__ __launch_bounds__(256, 2) void flash_attn(float* __restrict__ O) {
    extern __shared__ float sm[];
    float (*Qs)[PAD] = (float(*)[PAD])sm;
    float (*Ks)[PAD] = (float(*)[PAD])(sm + 64 * PAD);
    float (*Vs)[PAD] = (float(*)[PAD])(sm + 2 * 64 * PAD);
    float (*Ps)[PAD] = (float(*)[PAD])(sm + 3 * 64 * PAD);

    // Load-balanced schedule: classic bid->SM map has period 148, so blocks
    // bid and bid+148 share an SM; their tile counts sum to (64-x)+(x+1)=65.
    const int bid = blockIdx.x;
    int qt, b;
    if (bid < 148) { qt = 63 - (bid >> 2); b = bid & 3; }
    else           { qt = (bid - 148) >> 2; b = (bid - 148) & 3; }

    const int tid = threadIdx.x;
    const int tx  = tid & 15;
    const int ty  = tid >> 4;
    const int r0  = ty * 4;   // this thread's 4 query rows (tile-local)
    const int c0  = tx * 4;   // this thread's 4 keys (QK) / 4 dims (PV)
    const float scale = 0.125f;  // 64^-0.5
    const int i0 = qt * 64;

    // ---- Load Q tile (pre-scaled) ----
    const float* Qg = g_Q + ((size_t)b * SEQ + i0) * DH;
    for (int idx = tid; idx < 64 * 16; idx += 256) {
        int rr = idx >> 4, c4 = idx & 15;
        float4 v = *(const float4*)(Qg + rr * DH + c4 * 4);
        v.x *= scale; v.y *= scale; v.z *= scale; v.w *= scale;
        *(float4*)&Qs[rr][c4 * 4] = v;
    }

    float m[4], l[4];
    float4 o[4];
#pragma unroll
    for (int i = 0; i < 4; i++) {
        m[i] = -INFINITY; l[i] = 0.f;
        o[i] = make_float4(0.f, 0.f, 0.f, 0.f);
    }

    for (int t = 0; t <= qt; t++) {
        const int j0 = t * 64;
        const float* Kg = g_K + ((size_t)b * SEQ + j0) * DH;
        const float* Vg = g_V + ((size_t)b * SEQ + j0) * DH;

        __syncthreads();  // previous PV readers done with Ks/Vs/Ps
        for (int idx = tid; idx < 64 * 16; idx += 256) {
            int rr = idx >> 4, c4 = idx & 15;
            *(float4*)&Ks[rr][c4 * 4] = *(const float4*)(Kg + rr * DH + c4 * 4);
            *(float4*)&Vs[rr][c4 * 4] = *(const float4*)(Vg + rr * DH + c4 * 4);
        }
        __syncthreads();

        // ---- Scores: 4x4 block, 64 FMAs per 8 LDS.128 ----
        float s[4][4];
#pragma unroll
        for (int i = 0; i < 4; i++)
#pragma unroll
            for (int j = 0; j < 4; j++) s[i][j] = 0.f;

#pragma unroll 4
        for (int d4 = 0; d4 < 16; d4++) {
            float4 q[4], k[4];
#pragma unroll
            for (int i = 0; i < 4; i++) q[i] = *(float4*)&Qs[r0 + i][d4 * 4];
#pragma unroll
            for (int j = 0; j < 4; j++) k[j] = *(float4*)&Ks[c0 + j][d4 * 4];
#pragma unroll
            for (int i = 0; i < 4; i++)
#pragma unroll
                for (int j = 0; j < 4; j++) {
                    s[i][j] = fmaf(q[i].x, k[j].x, s[i][j]);
                    s[i][j] = fmaf(q[i].y, k[j].y, s[i][j]);
                    s[i][j] = fmaf(q[i].z, k[j].z, s[i][j]);
                    s[i][j] = fmaf(q[i].w, k[j].w, s[i][j]);
                }
        }

        // Causal mask on the diagonal tile
        if (t == qt) {
#pragma unroll
            for (int i = 0; i < 4; i++)
#pragma unroll
                for (int j = 0; j < 4; j++)
                    if (c0 + j > r0 + i) s[i][j] = -INFINITY;
        }

        // ---- Online softmax (reduce across the 16 tx threads, lane bits 0-3) ----
        float alpha[4];
#pragma unroll
        for (int i = 0; i < 4; i++) {
            float mt = fmaxf(fmaxf(s[i][0], s[i][1]), fmaxf(s[i][2], s[i][3]));
            mt = fmaxf(mt, __shfl_xor_sync(0xffffffffu, mt, 1));
            mt = fmaxf(mt, __shfl_xor_sync(0xffffffffu, mt, 2));
            mt = fmaxf(mt, __shfl_xor_sync(0xffffffffu, mt, 4));
            mt = fmaxf(mt, __shfl_xor_sync(0xffffffffu, mt, 8));
            const float mnew = fmaxf(m[i], mt);
            alpha[i] = __expf(m[i] - mnew);  // 0 when m == -inf
            float lt = 0.f;
#pragma unroll
            for (int j = 0; j < 4; j++) {
                s[i][j] = __expf(s[i][j] - mnew);  // masked -> 0
                lt += s[i][j];
            }
            lt += __shfl_xor_sync(0xffffffffu, lt, 1);
            lt += __shfl_xor_sync(0xffffffffu, lt, 2);
            lt += __shfl_xor_sync(0xffffffffu, lt, 4);
            lt += __shfl_xor_sync(0xffffffffu, lt, 8);
            l[i] = l[i] * alpha[i] + lt;
            m[i] = mnew;
            o[i].x *= alpha[i]; o[i].y *= alpha[i];
            o[i].z *= alpha[i]; o[i].w *= alpha[i];
        }

        // ---- Write P tile (safe: previous PV finished before this tile's
        //      first __syncthreads) ----
#pragma unroll
        for (int i = 0; i < 4; i++)
            *(float4*)&Ps[r0 + i][c0] = make_float4(s[i][0], s[i][1], s[i][2], s[i][3]);
        __syncthreads();

        // ---- O += P @ V : 16 FMAs per (1 LDS.128 + 4 broadcast LDS.32) ----
#pragma unroll 8
        for (int k = 0; k < 64; k++) {
            float4 v4 = *(float4*)&Vs[k][c0];
            float p0 = Ps[r0 + 0][k];
            float p1 = Ps[r0 + 1][k];
            float p2 = Ps[r0 + 2][k];
            float p3 = Ps[r0 + 3][k];
            o[0].x = fmaf(p0, v4.x, o[0].x); o[0].y = fmaf(p0, v4.y, o[0].y);
            o[0].z = fmaf(p0, v4.z, o[0].z); o[0].w = fmaf(p0, v4.w, o[0].w);
            o[1].x = fmaf(p1, v4.x, o[1].x); o[1].y = fmaf(p1, v4.y, o[1].y);
            o[1].z = fmaf(p1, v4.z, o[1].z); o[1].w = fmaf(p1, v4.w, o[1].w);
            o[2].x = fmaf(p2, v4.x, o[2].x); o[2].y = fmaf(p2, v4.y, o[2].y);
            o[2].z = fmaf(p2, v4.z, o[2].z); o[2].w = fmaf(p2, v4.w, o[2].w);
            o[3].x = fmaf(p3, v4.x, o[3].x); o[3].y = fmaf(p3, v4.y, o[3].y);
            o[3].z = fmaf(p3, v4.z, o[3].z); o[3].w = fmaf(p3, v4.w, o[3].w);
        }
    }

    // ---- Finalize ----
#pragma unroll
    for (int i = 0; i < 4; i++) {
        const float inv = 1.f / l[i];
        float4 v = o[i];
        v.x *= inv; v.y *= inv; v.z *= inv; v.w *= inv;
        float* Og = O + ((size_t)b * SEQ + i0 + r0 + i) * DH + c0;
        *(float4*)Og = v;
    }
}

// ---------------------------------------------------------------------------
extern "C" void kernel_launch(void* const* d_in, const int* in_sizes, int n_in,
                              void* d_out, int out_size) {
    const float* X  = (const float*)d_in[0];
    const float* Wq = (const float*)d_in[1];
    const float* Wk = (const float*)d_in[2];
    const float* Wv = (const float*)d_in[3];
    float* O = (float*)d_out;

    const int smem_attn = 4 * 64 * PAD * sizeof(float);  // 69632 B
    static int attr_set = 0;
    if (!attr_set) {
        cudaFuncSetAttribute(flash_attn, cudaFuncAttributeMaxDynamicSharedMemorySize,
                             smem_attn);
        attr_set = 1;
    }

    dim3 gproj((BATCH * SEQ) / 64, 3);
    qkv_gemm<<<gproj, 256>>>(X, Wq, Wk, Wv);

    flash_attn<<<256, 256, smem_attn>>>(O);
}

// round 3
// speedup vs baseline: 2.0721x; 1.3418x over previous
#include <cuda_runtime.h>
#include <math.h>

#define BATCH 4
#define SEQ   4096
#define DIN   1024
#define DH    64
#define PAD   68   // qkv_gemm only

// Scratch for Q/K/V projections — __device__ globals, no allocation.
__device__ float g_Q[BATCH * SEQ * DH];
__device__ float g_K[BATCH * SEQ * DH];
__device__ float g_V[BATCH * SEQ * DH];

__device__ __forceinline__ float ex2(float x) {
    float r;
    asm("ex2.approx.ftz.f32 %0, %1;" : "=f"(r) : "f"(x));
    return r;
}

// ---------------------------------------------------------------------------
// QKV projection GEMM: Out[M,64] = X[M,1024] @ W[1024,64],  M = B*S = 16384
// ---------------------------------------------------------------------------
__global__ __launch_bounds__(256) void qkv_gemm(const float* __restrict__ X,
                                                const float* __restrict__ Wq,
                                                const float* __restrict__ Wk,
                                                const float* __restrict__ Wv) {
    __shared__ float Xs[64][17];
    __shared__ float Ws[16][PAD];

    const float* W   = (blockIdx.y == 0) ? Wq : (blockIdx.y == 1) ? Wk : Wv;
    float*       Out = (blockIdx.y == 0) ? g_Q : (blockIdx.y == 1) ? g_K : g_V;

    const int tid  = threadIdx.x;
    const int row0 = blockIdx.x * 64;
    const int tx   = tid & 15;
    const int ty   = tid >> 4;

    float acc[4][4];
#pragma unroll
    for (int i = 0; i < 4; i++)
#pragma unroll
        for (int j = 0; j < 4; j++) acc[i][j] = 0.f;

    for (int k0 = 0; k0 < DIN; k0 += 16) {
        {
            int r = tid >> 2, c4 = tid & 3;
            float4 v = *(const float4*)(X + (size_t)(row0 + r) * DIN + k0 + c4 * 4);
            Xs[r][c4 * 4 + 0] = v.x; Xs[r][c4 * 4 + 1] = v.y;
            Xs[r][c4 * 4 + 2] = v.z; Xs[r][c4 * 4 + 3] = v.w;
        }
        {
            int r = tid >> 4, c4 = tid & 15;
            float4 v = *(const float4*)(W + (size_t)(k0 + r) * DH + c4 * 4);
            *(float4*)&Ws[r][c4 * 4] = v;
        }
        __syncthreads();

#pragma unroll
        for (int kk = 0; kk < 16; kk++) {
            float a[4];
#pragma unroll
            for (int i = 0; i < 4; i++) a[i] = Xs[ty * 4 + i][kk];
            float4 b4 = *(float4*)&Ws[kk][tx * 4];
            float b[4] = {b4.x, b4.y, b4.z, b4.w};
#pragma unroll
            for (int i = 0; i < 4; i++)
#pragma unroll
                for (int j = 0; j < 4; j++) acc[i][j] = fmaf(a[i], b[j], acc[i][j]);
        }
        __syncthreads();
    }

#pragma unroll
    for (int i = 0; i < 4; i++) {
        float4 v = make_float4(acc[i][0], acc[i][1], acc[i][2], acc[i][3]);
        *(float4*)(Out + (size_t)(row0 + ty * 4 + i) * DH + tx * 4) = v;
    }
}

// ---------------------------------------------------------------------------
// Causal flash attention, fp32, online softmax, 2-D register blocking,
// XOR-swizzled K/V smem (conflict-free for stride-4-row float4 reads).
//
// Layout: tile = 64 rows x 16 float4-chunks, row stride 64 floats (256 B).
// Chunk c of row r stored at physical chunk  c ^ ((r>>2)&7).
//   - QK reads row 4*tx+j chunk d4 -> phys d4^(tx&7): 8 distinct bank-groups
//     across each LDS phase -> conflict-free.
//   - PV reads row 4*k4+j chunk tx -> phys tx^(k4&7): conflict-free.
//   - Loader writes row rr chunk c4 -> phys c4^((rr>>2)&7): conflict-free.
// Q and P tiles are unswizzled (all accesses are warp broadcasts / row-linear).
// ---------------------------------------------------------------------------
__global__ __launch_bounds__(256, 2) void flash_attn(float* __restrict__ O) {
    extern __shared__ float sm[];
    float* Qs = sm;                 // [64][64] row-major
    float* Ks = sm + 64 * 64;       // [64][16 chunks] swizzled
    float* Vs = sm + 2 * 64 * 64;   // swizzled
    float* Ps = sm + 3 * 64 * 64;   // [64][64] row-major

    // Balanced causal schedule: blocks bid and bid+148 co-reside on one SM;
    // their tile counts sum to (64-x)+(x+1) = 65.
    const int bid = blockIdx.x;
    int qt, b;
    if (bid < 148) { qt = 63 - (bid >> 2); b = bid & 3; }
    else           { qt = (bid - 148) >> 2; b = (bid - 148) & 3; }

    const int tid = threadIdx.x;
    const int tx  = tid & 15;
    const int ty  = tid >> 4;
    const int r0  = ty * 4;
    const int c0  = tx * 4;
    const int sx  = tx & 7;              // QK swizzle key for this thread
    // score scale folded with log2(e): softmax computed in exp2 domain
    const float scale = 0.125f * 1.44269504088896340736f;
    const int i0 = qt * 64;

    // ---- Load Q tile (pre-scaled, row-major) ----
    const float* Qg = g_Q + ((size_t)b * SEQ + i0) * DH;
    for (int idx = tid; idx < 64 * 16; idx += 256) {
        int rr = idx >> 4, c4 = idx & 15;
        float4 v = *(const float4*)(Qg + rr * DH + c4 * 4);
        v.x *= scale; v.y *= scale; v.z *= scale; v.w *= scale;
        *(float4*)(Qs + rr * 64 + c4 * 4) = v;
    }

    float m[4], l[4];
    float4 o[4];
#pragma unroll
    for (int i = 0; i < 4; i++) {
        m[i] = -INFINITY; l[i] = 0.f;
        o[i] = make_float4(0.f, 0.f, 0.f, 0.f);
    }

    for (int t = 0; t <= qt; t++) {
        const int j0 = t * 64;
        const float* Kg = g_K + ((size_t)b * SEQ + j0) * DH;
        const float* Vg = g_V + ((size_t)b * SEQ + j0) * DH;

        __syncthreads();  // prior PV readers done with Ks/Vs/Ps
        for (int idx = tid; idx < 64 * 16; idx += 256) {
            int rr = idx >> 4, c4 = idx & 15;
            int pc = (c4 ^ ((rr >> 2) & 7)) * 4;
            *(float4*)(Ks + rr * 64 + pc) = *(const float4*)(Kg + rr * DH + c4 * 4);
            *(float4*)(Vs + rr * 64 + pc) = *(const float4*)(Vg + rr * DH + c4 * 4);
        }
        __syncthreads();

        // ---- Scores: 4x4 block, 64 FMAs per 8 LDS.128 (all conflict-free) ----
        float s[4][4];
#pragma unroll
        for (int i = 0; i < 4; i++)
#pragma unroll
            for (int j = 0; j < 4; j++) s[i][j] = 0.f;

#pragma unroll 4
        for (int d4 = 0; d4 < 16; d4++) {
            float4 q[4], k[4];
            const int kc = (d4 ^ sx) * 4;  // swizzled chunk for rows 4*tx+j
#pragma unroll
            for (int i = 0; i < 4; i++)
                q[i] = *(float4*)(Qs + (r0 + i) * 64 + d4 * 4);
#pragma unroll
            for (int j = 0; j < 4; j++)
                k[j] = *(float4*)(Ks + (c0 + j) * 64 + kc);
#pragma unroll
            for (int i = 0; i < 4; i++)
#pragma unroll
                for (int j = 0; j < 4; j++) {
                    s[i][j] = fmaf(q[i].x, k[j].x, s[i][j]);
                    s[i][j] = fmaf(q[i].y, k[j].y, s[i][j]);
                    s[i][j] = fmaf(q[i].z, k[j].z, s[i][j]);
                    s[i][j] = fmaf(q[i].w, k[j].w, s[i][j]);
                }
        }

        // Causal mask on the diagonal tile
        if (t == qt) {
#pragma unroll
            for (int i = 0; i < 4; i++)
#pragma unroll
                for (int j = 0; j < 4; j++)
                    if (c0 + j > r0 + i) s[i][j] = -INFINITY;
        }

        // ---- Online softmax in exp2 domain ----
#pragma unroll
        for (int i = 0; i < 4; i++) {
            float mt = fmaxf(fmaxf(s[i][0], s[i][1]), fmaxf(s[i][2], s[i][3]));
            mt = fmaxf(mt, __shfl_xor_sync(0xffffffffu, mt, 1));
            mt = fmaxf(mt, __shfl_xor_sync(0xffffffffu, mt, 2));
            mt = fmaxf(mt, __shfl_xor_sync(0xffffffffu, mt, 4));
            mt = fmaxf(mt, __shfl_xor_sync(0xffffffffu, mt, 8));
            const float mnew  = fmaxf(m[i], mt);
            const float alpha = ex2(m[i] - mnew);  // 0 when m == -inf
            float lt = 0.f;
#pragma unroll
            for (int j = 0; j < 4; j++) {
                s[i][j] = ex2(s[i][j] - mnew);  // masked -> 0
                lt += s[i][j];
            }
            lt += __shfl_xor_sync(0xffffffffu, lt, 1);
            lt += __shfl_xor_sync(0xffffffffu, lt, 2);
            lt += __shfl_xor_sync(0xffffffffu, lt, 4);
            lt += __shfl_xor_sync(0xffffffffu, lt, 8);
            l[i] = l[i] * alpha + lt;
            m[i] = mnew;
            o[i].x *= alpha; o[i].y *= alpha;
            o[i].z *= alpha; o[i].w *= alpha;
        }

        // ---- Write P tile ----
#pragma unroll
        for (int i = 0; i < 4; i++)
            *(float4*)(Ps + (r0 + i) * 64 + c0) =
                make_float4(s[i][0], s[i][1], s[i][2], s[i][3]);
        __syncthreads();

        // ---- O += P @ V : 64 FMAs per 8 LDS.128 ----
#pragma unroll 4
        for (int k4 = 0; k4 < 16; k4++) {
            float4 p[4], v[4];
            const int vc = (tx ^ (k4 & 7)) * 4;  // swizzled chunk for rows 4*k4+j
#pragma unroll
            for (int i = 0; i < 4; i++)
                p[i] = *(float4*)(Ps + (r0 + i) * 64 + k4 * 4);
#pragma unroll
            for (int j = 0; j < 4; j++)
                v[j] = *(float4*)(Vs + (4 * k4 + j) * 64 + vc);
#pragma unroll
            for (int i = 0; i < 4; i++) {
                o[i].x = fmaf(p[i].x, v[0].x, o[i].x);
                o[i].y = fmaf(p[i].x, v[0].y, o[i].y);
                o[i].z = fmaf(p[i].x, v[0].z, o[i].z);
                o[i].w = fmaf(p[i].x, v[0].w, o[i].w);
                o[i].x = fmaf(p[i].y, v[1].x, o[i].x);
                o[i].y = fmaf(p[i].y, v[1].y, o[i].y);
                o[i].z = fmaf(p[i].y, v[1].z, o[i].z);
                o[i].w = fmaf(p[i].y, v[1].w, o[i].w);
                o[i].x = fmaf(p[i].z, v[2].x, o[i].x);
                o[i].y = fmaf(p[i].z, v[2].y, o[i].y);
                o[i].z = fmaf(p[i].z, v[2].z, o[i].z);
                o[i].w = fmaf(p[i].z, v[2].w, o[i].w);
                o[i].x = fmaf(p[i].w, v[3].x, o[i].x);
                o[i].y = fmaf(p[i].w, v[3].y, o[i].y);
                o[i].z = fmaf(p[i].w, v[3].z, o[i].z);
                o[i].w = fmaf(p[i].w, v[3].w, o[i].w);
            }
        }
    }

    // ---- Finalize ----
#pragma unroll
    for (int i = 0; i < 4; i++) {
        const float inv = 1.f / l[i];
        float4 v = o[i];
        v.x *= inv; v.y *= inv; v.z *= inv; v.w *= inv;
        float* Og = O + ((size_t)b * SEQ + i0 + r0 + i) * DH + c0;
        *(float4*)Og = v;
    }
}

// ---------------------------------------------------------------------------
extern "C" void kernel_launch(void* const* d_in, const int* in_sizes, int n_in,
                              void* d_out, int out_size) {
    const float* X  = (const float*)d_in[0];
    const float* Wq = (const float*)d_in[1];
    const float* Wk = (const float*)d_in[2];
    const float* Wv = (const float*)d_in[3];
    float* O = (float*)d_out;

    const int smem_attn = 4 * 64 * 64 * sizeof(float);  // 65536 B
    static int attr_set = 0;
    if (!attr_set) {
        cudaFuncSetAttribute(flash_attn, cudaFuncAttributeMaxDynamicSharedMemorySize,
                             smem_attn);
        attr_set = 1;
    }

    dim3 gproj((BATCH * SEQ) / 64, 3);
    qkv_gemm<<<gproj, 256>>>(X, Wq, Wk, Wv);

    flash_attn<<<256, 256, smem_attn>>>(O);
}

// round 4
// speedup vs baseline: 2.1239x; 1.0250x over previous
#include <cuda_runtime.h>
#include <math.h>

#define BATCH 4
#define SEQ   4096
#define DIN   1024
#define DH    64
#define PAD   68   // qkv_gemm only

// Scratch for Q/K/V projections — __device__ globals, no allocation.
__device__ float g_Q[BATCH * SEQ * DH];
__device__ float g_K[BATCH * SEQ * DH];
__device__ float g_V[BATCH * SEQ * DH];

typedef unsigned long long u64;

__device__ __forceinline__ float ex2(float x) {
    float r;
    asm("ex2.approx.ftz.f32 %0, %1;" : "=f"(r) : "f"(x));
    return r;
}
// packed fp32x2 helpers (Blackwell FFMA2 — only reachable via PTX)
__device__ __forceinline__ void fma2(u64& d, u64 a, u64 b) {
    asm("fma.rn.f32x2 %0, %1, %2, %0;" : "+l"(d) : "l"(a), "l"(b));
}
__device__ __forceinline__ void mul2(u64& d, u64 a) {
    asm("mul.rn.f32x2 %0, %0, %1;" : "+l"(d) : "l"(a));
}
__device__ __forceinline__ u64 rep2(float x) {
    u64 r;
    asm("mov.b64 %0, {%1, %1};" : "=l"(r) : "f"(x));
    return r;
}
__device__ __forceinline__ float unpack_add(u64 v) {
    float lo, hi;
    asm("mov.b64 {%0, %1}, %2;" : "=f"(lo), "=f"(hi) : "l"(v));
    return lo + hi;
}

// ---------------------------------------------------------------------------
// QKV projection GEMM: Out[M,64] = X[M,1024] @ W[1024,64],  M = B*S = 16384
// ---------------------------------------------------------------------------
__global__ __launch_bounds__(256) void qkv_gemm(const float* __restrict__ X,
                                                const float* __restrict__ Wq,
                                                const float* __restrict__ Wk,
                                                const float* __restrict__ Wv) {
    __shared__ float Xs[64][17];
    __shared__ float Ws[16][PAD];

    const float* W   = (blockIdx.y == 0) ? Wq : (blockIdx.y == 1) ? Wk : Wv;
    float*       Out = (blockIdx.y == 0) ? g_Q : (blockIdx.y == 1) ? g_K : g_V;

    const int tid  = threadIdx.x;
    const int row0 = blockIdx.x * 64;
    const int tx   = tid & 15;
    const int ty   = tid >> 4;

    float acc[4][4];
#pragma unroll
    for (int i = 0; i < 4; i++)
#pragma unroll
        for (int j = 0; j < 4; j++) acc[i][j] = 0.f;

    for (int k0 = 0; k0 < DIN; k0 += 16) {
        {
            int r = tid >> 2, c4 = tid & 3;
            float4 v = *(const float4*)(X + (size_t)(row0 + r) * DIN + k0 + c4 * 4);
            Xs[r][c4 * 4 + 0] = v.x; Xs[r][c4 * 4 + 1] = v.y;
            Xs[r][c4 * 4 + 2] = v.z; Xs[r][c4 * 4 + 3] = v.w;
        }
        {
            int r = tid >> 4, c4 = tid & 15;
            float4 v = *(const float4*)(W + (size_t)(k0 + r) * DH + c4 * 4);
            *(float4*)&Ws[r][c4 * 4] = v;
        }
        __syncthreads();

#pragma unroll
        for (int kk = 0; kk < 16; kk++) {
            float a[4];
#pragma unroll
            for (int i = 0; i < 4; i++) a[i] = Xs[ty * 4 + i][kk];
            float4 b4 = *(float4*)&Ws[kk][tx * 4];
            float b[4] = {b4.x, b4.y, b4.z, b4.w};
#pragma unroll
            for (int i = 0; i < 4; i++)
#pragma unroll
                for (int j = 0; j < 4; j++) acc[i][j] = fmaf(a[i], b[j], acc[i][j]);
        }
        __syncthreads();
    }

#pragma unroll
    for (int i = 0; i < 4; i++) {
        float4 v = make_float4(acc[i][0], acc[i][1], acc[i][2], acc[i][3]);
        *(float4*)(Out + (size_t)(row0 + ty * 4 + i) * DH + tx * 4) = v;
    }
}

// ---------------------------------------------------------------------------
// Causal flash attention: fp32 with packed f32x2 FMAs (FFMA2), online softmax,
// 2-D register blocking, XOR-swizzled K/V smem.
//
// QK pairs over the head-dim (q/k float4 -> natural (x,y),(z,w) 64-bit pairs;
// s2 holds even/odd partial sums, one scalar add at reduction time).
// PV pairs over output dims ((v.x,v.y),(v.z,v.w)); p scalars replicated via
// mov.b64 on the ALU pipe.
// ---------------------------------------------------------------------------
__global__ __launch_bounds__(256, 2) void flash_attn(float* __restrict__ O) {
    extern __shared__ float sm[];
    float* Qs = sm;                 // [64][64] row-major
    float* Ks = sm + 64 * 64;       // swizzled: chunk c of row r at c^((r>>2)&7)
    float* Vs = sm + 2 * 64 * 64;   // swizzled
    float* Ps = sm + 3 * 64 * 64;   // [64][64] row-major

    // Balanced causal schedule: blocks bid and bid+148 co-reside on one SM;
    // their tile counts sum to 65.
    const int bid = blockIdx.x;
    int qt, b;
    if (bid < 148) { qt = 63 - (bid >> 2); b = bid & 3; }
    else           { qt = (bid - 148) >> 2; b = (bid - 148) & 3; }

    const int tid = threadIdx.x;
    const int tx  = tid & 15;
    const int ty  = tid >> 4;
    const int r0  = ty * 4;
    const int c0  = tx * 4;
    const int sx  = tx & 7;
    const float scale = 0.125f * 1.44269504088896340736f;  // exp2-domain
    const int i0 = qt * 64;

    // ---- Load Q tile (pre-scaled, row-major) ----
    const float* Qg = g_Q + ((size_t)b * SEQ + i0) * DH;
    for (int idx = tid; idx < 64 * 16; idx += 256) {
        int rr = idx >> 4, c4 = idx & 15;
        float4 v = *(const float4*)(Qg + rr * DH + c4 * 4);
        v.x *= scale; v.y *= scale; v.z *= scale; v.w *= scale;
        *(float4*)(Qs + rr * 64 + c4 * 4) = v;
    }

    float m[4], l[4];
    u64 o2[4][2];  // packed output accumulators: [row][(xy),(zw)]
#pragma unroll
    for (int i = 0; i < 4; i++) {
        m[i] = -INFINITY; l[i] = 0.f;
        o2[i][0] = 0ull; o2[i][1] = 0ull;
    }

    for (int t = 0; t <= qt; t++) {
        const int j0 = t * 64;
        const float* Kg = g_K + ((size_t)b * SEQ + j0) * DH;
        const float* Vg = g_V + ((size_t)b * SEQ + j0) * DH;

        __syncthreads();
        for (int idx = tid; idx < 64 * 16; idx += 256) {
            int rr = idx >> 4, c4 = idx & 15;
            int pc = (c4 ^ ((rr >> 2) & 7)) * 4;
            *(float4*)(Ks + rr * 64 + pc) = *(const float4*)(Kg + rr * DH + c4 * 4);
            *(float4*)(Vs + rr * 64 + pc) = *(const float4*)(Vg + rr * DH + c4 * 4);
        }
        __syncthreads();

        // ---- Scores: 4x4 block, 32 FFMA2 per 8 LDS.128 ----
        u64 s2[4][4];
#pragma unroll
        for (int i = 0; i < 4; i++)
#pragma unroll
            for (int j = 0; j < 4; j++) s2[i][j] = 0ull;

#pragma unroll 4
        for (int d4 = 0; d4 < 16; d4++) {
            ulonglong2 q2[4], k2[4];
            const int kc = (d4 ^ sx) * 4;
#pragma unroll
            for (int i = 0; i < 4; i++)
                q2[i] = *(const ulonglong2*)(Qs + (r0 + i) * 64 + d4 * 4);
#pragma unroll
            for (int j = 0; j < 4; j++)
                k2[j] = *(const ulonglong2*)(Ks + (c0 + j) * 64 + kc);
#pragma unroll
            for (int i = 0; i < 4; i++)
#pragma unroll
                for (int j = 0; j < 4; j++) {
                    fma2(s2[i][j], q2[i].x, k2[j].x);
                    fma2(s2[i][j], q2[i].y, k2[j].y);
                }
        }

        // Reduce packed partials to scalars
        float s[4][4];
#pragma unroll
        for (int i = 0; i < 4; i++)
#pragma unroll
            for (int j = 0; j < 4; j++) s[i][j] = unpack_add(s2[i][j]);

        // Causal mask on the diagonal tile
        if (t == qt) {
#pragma unroll
            for (int i = 0; i < 4; i++)
#pragma unroll
                for (int j = 0; j < 4; j++)
                    if (c0 + j > r0 + i) s[i][j] = -INFINITY;
        }

        // ---- Online softmax in exp2 domain ----
#pragma unroll
        for (int i = 0; i < 4; i++) {
            float mt = fmaxf(fmaxf(s[i][0], s[i][1]), fmaxf(s[i][2], s[i][3]));
            mt = fmaxf(mt, __shfl_xor_sync(0xffffffffu, mt, 1));
            mt = fmaxf(mt, __shfl_xor_sync(0xffffffffu, mt, 2));
            mt = fmaxf(mt, __shfl_xor_sync(0xffffffffu, mt, 4));
            mt = fmaxf(mt, __shfl_xor_sync(0xffffffffu, mt, 8));
            const float mnew  = fmaxf(m[i], mt);
            const float alpha = ex2(m[i] - mnew);  // 0 when m == -inf
            float lt = 0.f;
#pragma unroll
            for (int j = 0; j < 4; j++) {
                s[i][j] = ex2(s[i][j] - mnew);  // masked -> 0
                lt += s[i][j];
            }
            lt += __shfl_xor_sync(0xffffffffu, lt, 1);
            lt += __shfl_xor_sync(0xffffffffu, lt, 2);
            lt += __shfl_xor_sync(0xffffffffu, lt, 4);
            lt += __shfl_xor_sync(0xffffffffu, lt, 8);
            l[i] = l[i] * alpha + lt;
            m[i] = mnew;
            const u64 a2 = rep2(alpha);
            mul2(o2[i][0], a2);
            mul2(o2[i][1], a2);
        }

        // ---- Write P tile ----
#pragma unroll
        for (int i = 0; i < 4; i++)
            *(float4*)(Ps + (r0 + i) * 64 + c0) =
                make_float4(s[i][0], s[i][1], s[i][2], s[i][3]);
        __syncthreads();

        // ---- O += P @ V : 32 FFMA2 + 16 ALU packs per 8 LDS.128 ----
#pragma unroll 4
        for (int k4 = 0; k4 < 16; k4++) {
            float4 p[4];
            ulonglong2 v2[4];
            const int vc = (tx ^ (k4 & 7)) * 4;
#pragma unroll
            for (int i = 0; i < 4; i++)
                p[i] = *(float4*)(Ps + (r0 + i) * 64 + k4 * 4);
#pragma unroll
            for (int j = 0; j < 4; j++)
                v2[j] = *(const ulonglong2*)(Vs + (4 * k4 + j) * 64 + vc);
#pragma unroll
            for (int i = 0; i < 4; i++) {
                u64 a;
                a = rep2(p[i].x);
                fma2(o2[i][0], a, v2[0].x); fma2(o2[i][1], a, v2[0].y);
                a = rep2(p[i].y);
                fma2(o2[i][0], a, v2[1].x); fma2(o2[i][1], a, v2[1].y);
                a = rep2(p[i].z);
                fma2(o2[i][0], a, v2[2].x); fma2(o2[i][1], a, v2[2].y);
                a = rep2(p[i].w);
                fma2(o2[i][0], a, v2[3].x); fma2(o2[i][1], a, v2[3].y);
            }
        }
    }

    // ---- Finalize ----
#pragma unroll
    for (int i = 0; i < 4; i++) {
        const u64 inv = rep2(1.f / l[i]);
        mul2(o2[i][0], inv);
        mul2(o2[i][1], inv);
        ulonglong2 ov;
        ov.x = o2[i][0]; ov.y = o2[i][1];
        float* Og = O + ((size_t)b * SEQ + i0 + r0 + i) * DH + c0;
        *(ulonglong2*)Og = ov;
    }
}

// ---------------------------------------------------------------------------
extern "C" void kernel_launch(void* const* d_in, const int* in_sizes, int n_in,
                              void* d_out, int out_size) {
    const float* X  = (const float*)d_in[0];
    const float* Wq = (const float*)d_in[1];
    const float* Wk = (const float*)d_in[2];
    const float* Wv = (const float*)d_in[3];
    float* O = (float*)d_out;

    const int smem_attn = 4 * 64 * 64 * sizeof(float);  // 65536 B
    static int attr_set = 0;
    if (!attr_set) {
        cudaFuncSetAttribute(flash_attn, cudaFuncAttributeMaxDynamicSharedMemorySize,
                             smem_attn);
        attr_set = 1;
    }

    dim3 gproj((BATCH * SEQ) / 64, 3);
    qkv_gemm<<<gproj, 256>>>(X, Wq, Wk, Wv);

    flash_attn<<<256, 256, smem_attn>>>(O);
}